// round 6
// baseline (speedup 1.0000x reference)
#include <cuda_runtime.h>
#include <cuda_bf16.h>
#include <math.h>
#include <stdint.h>

// ---------------- problem constants ----------------
#define T_TOK  2048
#define HID    4096
#define NH     32
#define DN     128   // qk_nope
#define DR     64    // qk_rope
#define DH     192   // qk_head
#define DV     128   // v_head
#define QL     1536  // q_lora
#define KVL    512   // kv_lora

// ---------------- device scratch ----------------
__device__ float g_qa    [(size_t)T_TOK * QL];
__device__ float g_q     [(size_t)T_TOK * NH * DH];
__device__ float g_kva   [(size_t)T_TOK * (KVL + DR)];
__device__ float g_kv    [(size_t)T_TOK * NH * (DN + DV)];
__device__ float g_kfull [(size_t)T_TOK * NH * DH];
__device__ float g_s     [(size_t)NH * T_TOK * T_TOK];
__device__ float g_attn  [(size_t)T_TOK * NH * DV];
__device__ float g_rowsum[(size_t)NH * T_TOK];
__device__ float g_vt    [(size_t)NH * DV * T_TOK];     // v transposed per head [h][dv][t]
// tf32-rounded (and transposed, for weights) copies of raw inputs
__device__ float g_hidr  [(size_t)T_TOK * HID];
__device__ float g_wqa   [(size_t)QL * HID];            // [n][k]
__device__ float g_wqb   [(size_t)NH * DH * QL];        // [n][k]
__device__ float g_wkva  [(size_t)(KVL + DR) * HID];    // [n][k]
__device__ float g_wkvb  [(size_t)NH * (DN + DV) * KVL];// [n][k]
__device__ float g_wo    [(size_t)HID * NH * DV];       // [n][k]

// ---------------- helpers ----------------
__device__ __forceinline__ float round_tf32(float x) {
    float y;
    asm("cvt.rna.tf32.f32 %0, %1;" : "=f"(y) : "f"(x));
    return y;
}

__device__ __forceinline__ void mma_tf32(float* c, const uint32_t* a, const uint32_t* b) {
    asm volatile(
        "mma.sync.aligned.m16n8k8.row.col.f32.tf32.tf32.f32 "
        "{%0,%1,%2,%3}, {%4,%5,%6,%7}, {%8,%9}, {%0,%1,%2,%3};"
        : "+f"(c[0]), "+f"(c[1]), "+f"(c[2]), "+f"(c[3])
        : "r"(a[0]), "r"(a[1]), "r"(a[2]), "r"(a[3]), "r"(b[0]), "r"(b[1]));
}

__device__ __forceinline__ void ldsm_x4(uint32_t& r0, uint32_t& r1, uint32_t& r2,
                                        uint32_t& r3, uint32_t addr) {
    asm volatile("ldmatrix.sync.aligned.m8n8.x4.shared.b16 {%0,%1,%2,%3}, [%4];"
                 : "=r"(r0), "=r"(r1), "=r"(r2), "=r"(r3) : "r"(addr));
}

#define CP_ASYNC16(dst_u32, src_ptr, sz) \
    asm volatile("cp.async.cg.shared.global [%0], [%1], 16, %2;" \
        :: "r"(dst_u32), "l"(src_ptr), "r"(sz))
#define CP_COMMIT() asm volatile("cp.async.commit_group;" ::: "memory")
#define CP_WAIT1()  asm volatile("cp.async.wait_group 1;" ::: "memory")
#define CP_WAIT0()  asm volatile("cp.async.wait_group 0;" ::: "memory")

// ---------------- elementwise tf32 rounding pass ----------------
__global__ void round_pass_kernel(const float* __restrict__ in, float* __restrict__ out,
                                  int n4)
{
    const int stride = gridDim.x * blockDim.x;
    for (int i = blockIdx.x * blockDim.x + threadIdx.x; i < n4; i += stride) {
        float4 v = ((const float4*)in)[i];
        v.x = round_tf32(v.x); v.y = round_tf32(v.y);
        v.z = round_tf32(v.z); v.w = round_tf32(v.w);
        ((float4*)out)[i] = v;
    }
}

// ---------------- fused round + transpose: in[R][C] -> out[C][R] ----------------
__global__ void transpose_round_kernel(const float* __restrict__ in,
                                       float* __restrict__ out, int R, int C)
{
    __shared__ float tile[32][33];
    const int c0 = blockIdx.x * 32;
    const int r0 = blockIdx.y * 32;
    const int tx = threadIdx.x;
#pragma unroll
    for (int i = threadIdx.y; i < 32; i += 8)
        tile[i][tx] = round_tf32(in[(size_t)(r0 + i) * C + c0 + tx]);
    __syncthreads();
#pragma unroll
    for (int i = threadIdx.y; i < 32; i += 8)
        out[(size_t)(c0 + i) * R + r0 + tx] = tile[tx][i];
}

// ---------------- transpose v slice of kv into g_vt (values already rounded) ----------------
__global__ void vtrans_kernel()
{
    __shared__ float tile[32][33];
    const int t0  = blockIdx.x * 32;
    const int dv0 = blockIdx.y * 32;
    const int h   = blockIdx.z;
    const int tx  = threadIdx.x;
#pragma unroll
    for (int i = threadIdx.y; i < 32; i += 8)
        tile[i][tx] = g_kv[(size_t)(t0 + i) * (NH * (DN + DV)) + h * (DN + DV) + DN + dv0 + tx];
    __syncthreads();
#pragma unroll
    for (int i = threadIdx.y; i < 32; i += 8)
        g_vt[(size_t)h * DV * T_TOK + (size_t)(dv0 + i) * T_TOK + t0 + tx] = tile[tx][i];
}

// ---------------- tensor-core tf32 GEMM (mma.sync + cp.async + ldmatrix) ----------------
// C[m,n] = alpha * sum_k A[m,k] * B[n,k]   (B always n-major / K-major rows)
// BM=BN=128, BK=64, 256 threads (8 warps: 4m x 2n), warp tile 32x64, 2-stage cp.async.
// Inputs pre-rounded to tf32. SKIPN: causal tile skip. CLAMPK: K->min(K,m0+128).
// ROUNDC: round output at store.
#define STG_WORDS 8704
#define GEMM_SMEM_BYTES (4 * STG_WORDS * 4)

template <bool SKIPN, bool CLAMPK, bool ROUNDC>
__global__ __launch_bounds__(256)
void tmma_gemm(const float* __restrict__ A, const float* __restrict__ B,
               float* __restrict__ C,
               int M, int N, int K, int lda, int ldb, int ldc,
               long long sA, long long sB, long long sC, float alpha)
{
    extern __shared__ float smf[];
    float* Abuf = smf;                   // 2 x 8704
    float* Bbuf = smf + 2 * STG_WORDS;   // 2 x 8704

    const int tid  = threadIdx.x;
    const int wid  = tid >> 5;
    const int lane = tid & 31;
    const int g    = lane >> 2;
    const int tig  = lane & 3;

    const int wm = (wid >> 1) * 32;
    const int wn = (wid & 1) * 64;

    const int z  = blockIdx.z;
    const int m0 = blockIdx.y * 128;
    const int n0 = blockIdx.x * 128;

    if (SKIPN && n0 > m0 + 127) return;

    A += (size_t)z * sA;
    B += (size_t)z * sB;
    C += (size_t)z * sC;

    int Keff = K;
    if (CLAMPK) Keff = min(K, m0 + 128);
    const int nkt = Keff >> 6;

    const uint32_t a_sm = (uint32_t)__cvta_generic_to_shared(Abuf);
    const uint32_t b_sm = (uint32_t)__cvta_generic_to_shared(Bbuf);

    auto load_tile = [&](int kt, int st) {
        const int k0 = kt << 6;
        const uint32_t asb = a_sm + (uint32_t)st * STG_WORDS * 4;
        const uint32_t bsb = b_sm + (uint32_t)st * STG_WORDS * 4;
#pragma unroll
        for (int i = 0; i < 8; i++) {
            const int idx = i * 256 + tid;
            const int row = idx >> 4;
            const int c4  = (idx & 15) * 4;
            const uint32_t dst = asb + (uint32_t)(row * 68 + c4) * 4;
            const float* src = A + (size_t)(m0 + row) * lda + k0 + c4;
            CP_ASYNC16(dst, src, 16);
        }
#pragma unroll
        for (int i = 0; i < 8; i++) {
            const int idx = i * 256 + tid;
            const int row = idx >> 4;
            const int c4  = (idx & 15) * 4;
            const bool in = (n0 + row < N);
            const uint32_t dst = bsb + (uint32_t)(row * 68 + c4) * 4;
            const float* src = in ? (B + (size_t)(n0 + row) * ldb + k0 + c4) : B;
            CP_ASYNC16(dst, src, in ? 16 : 0);
        }
    };

    float acc[2][8][4];
#pragma unroll
    for (int mt = 0; mt < 2; mt++)
#pragma unroll
        for (int nt = 0; nt < 8; nt++)
#pragma unroll
            for (int r = 0; r < 4; r++) acc[mt][nt][r] = 0.0f;

    // ldmatrix per-thread row offsets (within warp tile), element units
    const int lr   = lane & 7;          // row within matrix
    const int lhk  = (lane >> 3) & 1;   // A: m-half selector / B: k-half selector
    const int lhi  = lane >> 4;         // A: k-half selector / B: n-half selector

    load_tile(0, 0);
    CP_COMMIT();

    for (int kt = 0; kt < nkt; kt++) {
        if (kt + 1 < nkt) {
            load_tile(kt + 1, (kt + 1) & 1);
            CP_COMMIT();
            CP_WAIT1();
        } else {
            CP_WAIT0();
        }
        __syncthreads();

        const uint32_t asb = a_sm + (uint32_t)(kt & 1) * STG_WORDS * 4;
        const uint32_t bsb = b_sm + (uint32_t)(kt & 1) * STG_WORDS * 4;

#pragma unroll
        for (int ks = 0; ks < 8; ks++) {
            const int kk = ks * 8;
            // A fragments: matrices {m0-7|klo, m8-15|klo, m0-7|khi, m8-15|khi}
            uint32_t af[2][4];
#pragma unroll
            for (int mt = 0; mt < 2; mt++) {
                const int row = wm + mt * 16 + lhk * 8 + lr;
                const uint32_t addr = asb + (uint32_t)(row * 68 + kk + lhi * 4) * 4;
                ldsm_x4(af[mt][0], af[mt][1], af[mt][2], af[mt][3], addr);
            }
            // B fragments: matrices {n0-7|klo, n0-7|khi, n8-15|klo, n8-15|khi}
            uint32_t bf[8][2];
#pragma unroll
            for (int p = 0; p < 4; p++) {
                const int row = wn + p * 16 + lhi * 8 + lr;
                const uint32_t addr = bsb + (uint32_t)(row * 68 + kk + lhk * 4) * 4;
                ldsm_x4(bf[2 * p][0], bf[2 * p][1], bf[2 * p + 1][0], bf[2 * p + 1][1], addr);
            }
#pragma unroll
            for (int mt = 0; mt < 2; mt++)
#pragma unroll
                for (int nt = 0; nt < 8; nt++)
                    mma_tf32(acc[mt][nt], af[mt], bf[nt]);
        }
        __syncthreads();
    }

    // ---- epilogue ----
#pragma unroll
    for (int mt = 0; mt < 2; mt++) {
#pragma unroll
        for (int nt = 0; nt < 8; nt++) {
            const int col = n0 + wn + nt * 8 + 2 * tig;
            if (col < N) {
                const int r0 = m0 + wm + mt * 16 + g;
                float o0 = alpha * acc[mt][nt][0], o1 = alpha * acc[mt][nt][1];
                float o2 = alpha * acc[mt][nt][2], o3 = alpha * acc[mt][nt][3];
                if (ROUNDC) {
                    o0 = round_tf32(o0); o1 = round_tf32(o1);
                    o2 = round_tf32(o2); o3 = round_tf32(o3);
                }
                *(float2*)&C[(size_t)r0 * ldc + col]       = make_float2(o0, o1);
                *(float2*)&C[(size_t)(r0 + 8) * ldc + col] = make_float2(o2, o3);
            }
        }
    }
}

// ---------------- rmsnorm (writes tf32-rounded output) ----------------
__global__ void rmsnorm_kernel(float* __restrict__ x, const float* __restrict__ g,
                               int rowstride, int w)
{
    const int row = blockIdx.x;
    float* p = x + (size_t)row * rowstride;
    __shared__ float red[256];
    float s = 0.0f;
    for (int c = threadIdx.x; c < w; c += 256) { float v = p[c]; s += v * v; }
    red[threadIdx.x] = s;
    __syncthreads();
    for (int o = 128; o > 0; o >>= 1) {
        if (threadIdx.x < o) red[threadIdx.x] += red[threadIdx.x + o];
        __syncthreads();
    }
    const float r = rsqrtf(red[0] / (float)w + 1e-6f);
    for (int c = threadIdx.x; c < w; c += 256)
        p[c] = round_tf32(p[c] * r * g[c]);
}

// ---------------- interleaved RoPE (writes rounded; optionally rounds nope part) ----------------
__global__ void rope_kernel(float* __restrict__ base, const int* __restrict__ positions,
                            int rowstride, int headstride, int offset, int round_nope)
{
    const int t = blockIdx.x;
    const int h = blockIdx.y;
    const int i = threadIdx.x;  // 0..31
    float* hp = base + (size_t)t * rowstride + h * headstride;
    float* p = hp + offset;
    const float pos = (float)positions[t];
    const float inv = powf(10000.0f, -(float)(2 * i) / 64.0f);
    float sn, cs;
    sincosf(pos * inv, &sn, &cs);
    const float x1 = p[2 * i];
    const float x2 = p[2 * i + 1];
    p[2 * i]     = round_tf32(x1 * cs - x2 * sn);
    p[2 * i + 1] = round_tf32(x1 * sn + x2 * cs);
    if (round_nope) {
#pragma unroll
        for (int j = 0; j < 4; j++)
            hp[i * 4 + j] = round_tf32(hp[i * 4 + j]);
    }
}

// ---------------- build k_full ----------------
__global__ void kfull_kernel()
{
    const int t = blockIdx.x;
    const int h = blockIdx.y;
    const int d = threadIdx.x;
    float v;
    if (d < DN) v = g_kv[(size_t)t * (NH * (DN + DV)) + h * (DN + DV) + d];
    else        v = g_kva[(size_t)t * (KVL + DR) + KVL + (d - DN)];
    g_kfull[(size_t)t * (NH * DH) + h * DH + d] = v;
}

// ---------------- causal softmax: stores rounded exp, sums unrounded ----------------
__global__ void softmax_kernel(const int* __restrict__ positions)
{
    const int q = blockIdx.x;
    const int h = blockIdx.y;
    float* row = g_s + ((size_t)h * T_TOK + q) * T_TOK;
    const int pq = positions[q];
    const int jmax = ((q >> 7) + 1) << 7;
    __shared__ float red[256];
    const int tid = threadIdx.x;

    float m = -INFINITY;
    for (int j = tid; j < jmax; j += 256)
        if (positions[j] <= pq) m = fmaxf(m, row[j]);
    red[tid] = m;
    __syncthreads();
    for (int o = 128; o > 0; o >>= 1) {
        if (tid < o) red[tid] = fmaxf(red[tid], red[tid + o]);
        __syncthreads();
    }
    m = red[0];
    __syncthreads();

    float s = 0.0f;
    for (int j = tid; j < jmax; j += 256) {
        float v = 0.0f;
        if (positions[j] <= pq) { v = __expf(row[j] - m); s += v; }
        row[j] = round_tf32(v);
    }
    red[tid] = s;
    __syncthreads();
    for (int o = 128; o > 0; o >>= 1) {
        if (tid < o) red[tid] += red[tid + o];
        __syncthreads();
    }
    if (tid == 0) g_rowsum[(size_t)h * T_TOK + q] = red[0];
}

// ---------------- normalize attn rows (writes rounded) ----------------
__global__ void attn_norm_kernel()
{
    const int t = blockIdx.x;
    float* p = g_attn + (size_t)t * (NH * DV);
    for (int c = threadIdx.x; c < NH * DV; c += 256) {
        const int h = c >> 7;
        p[c] = round_tf32(p[c] * (1.0f / g_rowsum[(size_t)h * T_TOK + t]));
    }
}

// ---------------- launcher ----------------
extern "C" void kernel_launch(void* const* d_in, const int* in_sizes, int n_in,
                              void* d_out, int out_size)
{
    const int*   positions = (const int*)  d_in[0];
    const float* hidden    = (const float*)d_in[1];
    const float* wq_a      = (const float*)d_in[2];
    const float* gq        = (const float*)d_in[3];
    const float* wq_b      = (const float*)d_in[4];
    const float* wkv_a     = (const float*)d_in[5];
    const float* gkv       = (const float*)d_in[6];
    const float* wkv_b     = (const float*)d_in[7];
    const float* wo        = (const float*)d_in[8];
    float* out = (float*)d_out;

    float *qa, *q, *kva, *kv, *kfull, *s, *attn, *vt;
    float *hidr, *wqa, *wqb, *wkva, *wkvb, *wor;
    cudaGetSymbolAddress((void**)&qa,    g_qa);
    cudaGetSymbolAddress((void**)&q,     g_q);
    cudaGetSymbolAddress((void**)&kva,   g_kva);
    cudaGetSymbolAddress((void**)&kv,    g_kv);
    cudaGetSymbolAddress((void**)&kfull, g_kfull);
    cudaGetSymbolAddress((void**)&s,     g_s);
    cudaGetSymbolAddress((void**)&attn,  g_attn);
    cudaGetSymbolAddress((void**)&vt,    g_vt);
    cudaGetSymbolAddress((void**)&hidr,  g_hidr);
    cudaGetSymbolAddress((void**)&wqa,   g_wqa);
    cudaGetSymbolAddress((void**)&wqb,   g_wqb);
    cudaGetSymbolAddress((void**)&wkva,  g_wkva);
    cudaGetSymbolAddress((void**)&wkvb,  g_wkvb);
    cudaGetSymbolAddress((void**)&wor,   g_wo);

    static bool attr_done = false;
    if (!attr_done) {
        cudaFuncSetAttribute(tmma_gemm<false,false,false>,
            cudaFuncAttributeMaxDynamicSharedMemorySize, GEMM_SMEM_BYTES);
        cudaFuncSetAttribute(tmma_gemm<false,false,true>,
            cudaFuncAttributeMaxDynamicSharedMemorySize, GEMM_SMEM_BYTES);
        cudaFuncSetAttribute(tmma_gemm<true,false,false>,
            cudaFuncAttributeMaxDynamicSharedMemorySize, GEMM_SMEM_BYTES);
        cudaFuncSetAttribute(tmma_gemm<false,true,false>,
            cudaFuncAttributeMaxDynamicSharedMemorySize, GEMM_SMEM_BYTES);
        attr_done = true;
    }

    const float scale = 1.0f / sqrtf((float)DH);
    const dim3 blk(256);
    const int  shm = GEMM_SMEM_BYTES;
    const dim3 tblk(32, 8);

    // 0. round hidden; round+transpose weights to [n][k]
    round_pass_kernel<<<1024, 256>>>(hidden, hidr, (int)((size_t)T_TOK * HID / 4));
    transpose_round_kernel<<<dim3(QL/32, HID/32), tblk>>>(wq_a, wqa, HID, QL);
    transpose_round_kernel<<<dim3(NH*DH/32, QL/32), tblk>>>(wq_b, wqb, QL, NH*DH);
    transpose_round_kernel<<<dim3((KVL+DR)/32, HID/32), tblk>>>(wkv_a, wkva, HID, KVL+DR);
    transpose_round_kernel<<<dim3(NH*(DN+DV)/32, KVL/32), tblk>>>(wkv_b, wkvb, KVL, NH*(DN+DV));
    transpose_round_kernel<<<dim3(HID/32, NH*DV/32), tblk>>>(wo, wor, NH*DV, HID);

    // 1. qa = hidr @ wqa^T           [2048,1536] K=4096
    tmma_gemm<false,false,false><<<dim3(QL/128, T_TOK/128, 1), blk, shm>>>(
        hidr, wqa, qa, T_TOK, QL, HID, HID, HID, QL, 0, 0, 0, 1.0f);

    // 2. rmsnorm(qa) -> rounded
    rmsnorm_kernel<<<T_TOK, 256>>>(qa, gq, QL, QL);

    // 3. q = qln @ wqb^T             [2048,6144] K=1536
    tmma_gemm<false,false,false><<<dim3(NH*DH/128, T_TOK/128, 1), blk, shm>>>(
        qa, wqb, q, T_TOK, NH*DH, QL, QL, QL, NH*DH, 0, 0, 0, 1.0f);

    // 4. kva = hidr @ wkva^T         [2048,576] K=4096
    tmma_gemm<false,false,false><<<dim3((KVL+DR+127)/128, T_TOK/128, 1), blk, shm>>>(
        hidr, wkva, kva, T_TOK, KVL+DR, HID, HID, HID, KVL+DR, 0, 0, 0, 1.0f);

    // 5. rmsnorm first 512 cols of kva -> rounded
    rmsnorm_kernel<<<T_TOK, 256>>>(kva, gkv, KVL+DR, KVL);

    // 6. kv = ckv_ln @ wkvb^T        [2048,8192] K=512  (epilogue rounds)
    tmma_gemm<false,false,true><<<dim3(NH*(DN+DV)/128, T_TOK/128, 1), blk, shm>>>(
        kva, wkvb, kv, T_TOK, NH*(DN+DV), KVL, KVL+DR, KVL, NH*(DN+DV),
        0, 0, 0, 1.0f);

    // 7. rope q_pe (+ round q_nope)
    rope_kernel<<<dim3(T_TOK, NH), 32>>>(q, positions, NH*DH, DH, DN, 1);

    // 8. rope k_pe
    rope_kernel<<<dim3(T_TOK, 1), 32>>>(kva, positions, KVL+DR, 0, KVL, 0);

    // 9. k_full + v^T
    kfull_kernel<<<dim3(T_TOK, NH), DH>>>();
    vtrans_kernel<<<dim3(T_TOK/32, DV/32, NH), tblk>>>();

    // 10. scores[h] = scale * q[h] @ kfull[h]^T   (causal tile skip)
    tmma_gemm<true,false,false><<<dim3(T_TOK/128, T_TOK/128, NH), blk, shm>>>(
        q, kfull, s, T_TOK, T_TOK, DH, NH*DH, NH*DH, T_TOK,
        (long long)DH, (long long)DH, (long long)T_TOK*T_TOK, scale);

    // 11. causal softmax (stores rounded exp, sums fp32)
    softmax_kernel<<<dim3(T_TOK, NH), 256>>>(positions);

    // 12. attn[h] = exp_probs[h] @ vt[h]^T   (causal K clamp)
    tmma_gemm<false,true,false><<<dim3(1, T_TOK/128, NH), blk, shm>>>(
        s, vt, attn, T_TOK, DV, T_TOK, T_TOK, T_TOK, NH*DV,
        (long long)T_TOK*T_TOK, (long long)DV*T_TOK, (long long)DV, 1.0f);

    // 12b. normalize attn -> rounded
    attn_norm_kernel<<<T_TOK, 256>>>();

    // 13. out = attn @ wo^T           [2048,4096]
    tmma_gemm<false,false,false><<<dim3(HID/128, T_TOK/128, 1), blk, shm>>>(
        attn, wor, out, T_TOK, HID, NH*DV, NH*DV, NH*DV, HID, 0, 0, 0, 1.0f);
}

// round 7
// speedup vs baseline: 1.1311x; 1.1311x over previous
#include <cuda_runtime.h>
#include <cuda_bf16.h>
#include <math.h>
#include <stdint.h>

// ---------------- problem constants ----------------
#define T_TOK  2048
#define HID    4096
#define NH     32
#define DN     128   // qk_nope
#define DR     64    // qk_rope
#define DH     192   // qk_head
#define DV     128   // v_head
#define QL     1536  // q_lora
#define KVL    512   // kv_lora

// ---------------- device scratch ----------------
__device__ float g_qa    [(size_t)T_TOK * QL];
__device__ float g_q     [(size_t)T_TOK * NH * DH];
__device__ float g_kva   [(size_t)T_TOK * (KVL + DR)];
__device__ float g_kv    [(size_t)T_TOK * NH * (DN + DV)];
__device__ float g_kfull [(size_t)T_TOK * NH * DH];
__device__ float g_s     [(size_t)NH * T_TOK * T_TOK];
__device__ float g_attn  [(size_t)T_TOK * NH * DV];
__device__ float g_rowsum[(size_t)NH * T_TOK];
__device__ float g_vt    [(size_t)NH * DV * T_TOK];     // v transposed per head [h][dv][t]
// tf32-rounded (and transposed, for weights) copies of raw inputs
__device__ float g_hidr  [(size_t)T_TOK * HID];
__device__ float g_wqa   [(size_t)QL * HID];            // [n][k]
__device__ float g_wqb   [(size_t)NH * DH * QL];        // [n][k]
__device__ float g_wkva  [(size_t)(KVL + DR) * HID];    // [n][k]
__device__ float g_wkvb  [(size_t)NH * (DN + DV) * KVL];// [n][k]
__device__ float g_wo    [(size_t)HID * NH * DV];       // [n][k]

// ---------------- helpers ----------------
__device__ __forceinline__ float round_tf32(float x) {
    float y;
    asm("cvt.rna.tf32.f32 %0, %1;" : "=f"(y) : "f"(x));
    return y;
}

__device__ __forceinline__ void mma_tf32(float* c, const uint32_t* a, const uint32_t* b) {
    asm volatile(
        "mma.sync.aligned.m16n8k8.row.col.f32.tf32.tf32.f32 "
        "{%0,%1,%2,%3}, {%4,%5,%6,%7}, {%8,%9}, {%0,%1,%2,%3};"
        : "+f"(c[0]), "+f"(c[1]), "+f"(c[2]), "+f"(c[3])
        : "r"(a[0]), "r"(a[1]), "r"(a[2]), "r"(a[3]), "r"(b[0]), "r"(b[1]));
}

__device__ __forceinline__ void ldsm_x4(uint32_t& r0, uint32_t& r1, uint32_t& r2,
                                        uint32_t& r3, uint32_t addr) {
    asm volatile("ldmatrix.sync.aligned.m8n8.x4.shared.b16 {%0,%1,%2,%3}, [%4];"
                 : "=r"(r0), "=r"(r1), "=r"(r2), "=r"(r3) : "r"(addr));
}

#define CP_ASYNC16(dst_u32, src_ptr, sz) \
    asm volatile("cp.async.cg.shared.global [%0], [%1], 16, %2;" \
        :: "r"(dst_u32), "l"(src_ptr), "r"(sz))
#define CP_COMMIT() asm volatile("cp.async.commit_group;" ::: "memory")
#define CP_WAIT1()  asm volatile("cp.async.wait_group 1;" ::: "memory")
#define CP_WAIT0()  asm volatile("cp.async.wait_group 0;" ::: "memory")

// ---------------- elementwise tf32 rounding pass ----------------
__global__ void round_pass_kernel(const float* __restrict__ in, float* __restrict__ out,
                                  int n4)
{
    const int stride = gridDim.x * blockDim.x;
    for (int i = blockIdx.x * blockDim.x + threadIdx.x; i < n4; i += stride) {
        float4 v = ((const float4*)in)[i];
        v.x = round_tf32(v.x); v.y = round_tf32(v.y);
        v.z = round_tf32(v.z); v.w = round_tf32(v.w);
        ((float4*)out)[i] = v;
    }
}

// ---------------- fused round + transpose: in[R][C] -> out[C][R] ----------------
__global__ void transpose_round_kernel(const float* __restrict__ in,
                                       float* __restrict__ out, int R, int C)
{
    __shared__ float tile[32][33];
    const int c0 = blockIdx.x * 32;
    const int r0 = blockIdx.y * 32;
    const int tx = threadIdx.x;
#pragma unroll
    for (int i = threadIdx.y; i < 32; i += 8)
        tile[i][tx] = round_tf32(in[(size_t)(r0 + i) * C + c0 + tx]);
    __syncthreads();
#pragma unroll
    for (int i = threadIdx.y; i < 32; i += 8)
        out[(size_t)(c0 + i) * R + r0 + tx] = tile[tx][i];
}

// ---------------- transpose v slice of kv into g_vt ----------------
__global__ void vtrans_kernel()
{
    __shared__ float tile[32][33];
    const int t0  = blockIdx.x * 32;
    const int dv0 = blockIdx.y * 32;
    const int h   = blockIdx.z;
    const int tx  = threadIdx.x;
#pragma unroll
    for (int i = threadIdx.y; i < 32; i += 8)
        tile[i][tx] = g_kv[(size_t)(t0 + i) * (NH * (DN + DV)) + h * (DN + DV) + DN + dv0 + tx];
    __syncthreads();
#pragma unroll
    for (int i = threadIdx.y; i < 32; i += 8)
        g_vt[(size_t)h * DV * T_TOK + (size_t)(dv0 + i) * T_TOK + t0 + tx] = tile[tx][i];
}

// ---------------- tensor-core tf32 GEMM: 3-stage cp.async multistage + ldmatrix ----------------
// C[m,n] = alpha * sum_k A[m,k] * B[n,k]   (both operands K-major)
// BM=BN=128, BK=64, 256 threads (8 warps: 4m x 2n), warp tile 32x64.
// SMEM: XOR-swizzled (16B chunk ^ (row&7)), no padding. Stage = 128x64 floats = 32KB.
// 3 stages x (A+B) = 192KB. Single __syncthreads per k-tile.
#define NSTAGE 3
#define STG_WORDS 8192
#define GEMM_SMEM_BYTES (2 * NSTAGE * STG_WORDS * 4)

template <bool SKIPN, bool CLAMPK, bool ROUNDC>
__global__ __launch_bounds__(256)
void tmma_gemm(const float* __restrict__ A, const float* __restrict__ B,
               float* __restrict__ C,
               int M, int N, int K, int lda, int ldb, int ldc,
               long long sA, long long sB, long long sC, float alpha)
{
    extern __shared__ float smf[];

    const int tid  = threadIdx.x;
    const int wid  = tid >> 5;
    const int lane = tid & 31;
    const int g    = lane >> 2;
    const int tig  = lane & 3;

    const int wm = (wid >> 1) * 32;
    const int wn = (wid & 1) * 64;

    const int z  = blockIdx.z;
    const int m0 = blockIdx.y * 128;
    const int n0 = blockIdx.x * 128;

    if (SKIPN && n0 > m0 + 127) return;

    A += (size_t)z * sA;
    B += (size_t)z * sB;
    C += (size_t)z * sC;

    int Keff = K;
    if (CLAMPK) Keff = min(K, m0 + 128);
    const int nkt = Keff >> 6;

    const uint32_t a_sm = (uint32_t)__cvta_generic_to_shared(smf);
    const uint32_t b_sm = a_sm + NSTAGE * STG_WORDS * 4;

    // precomputed per-thread load coordinates (8 chunks of A, 8 of B)
    const int lrow = tid >> 4;          // 0..15 (row group start, step 16)
    const int lchk = tid & 15;          // chunk 0..15

    auto load_tile = [&](int kt) {
        const int st = kt % NSTAGE;
        const int k0 = kt << 6;
        const uint32_t asb = a_sm + (uint32_t)st * STG_WORDS * 4;
        const uint32_t bsb = b_sm + (uint32_t)st * STG_WORDS * 4;
#pragma unroll
        for (int i = 0; i < 8; i++) {
            const int row = i * 16 + lrow;
            const uint32_t swz = (uint32_t)(lchk ^ (row & 7));
            const uint32_t dst = asb + (uint32_t)row * 256 + swz * 16;
            const float* src = A + (size_t)(m0 + row) * lda + k0 + lchk * 4;
            CP_ASYNC16(dst, src, 16);
        }
#pragma unroll
        for (int i = 0; i < 8; i++) {
            const int row = i * 16 + lrow;
            const bool in = (n0 + row < N);
            const uint32_t swz = (uint32_t)(lchk ^ (row & 7));
            const uint32_t dst = bsb + (uint32_t)row * 256 + swz * 16;
            const float* src = in ? (B + (size_t)(n0 + row) * ldb + k0 + lchk * 4) : B;
            CP_ASYNC16(dst, src, in ? 16 : 0);
        }
    };

    float acc[2][8][4];
#pragma unroll
    for (int mt = 0; mt < 2; mt++)
#pragma unroll
        for (int nt = 0; nt < 8; nt++)
#pragma unroll
            for (int r = 0; r < 4; r++) acc[mt][nt][r] = 0.0f;

    // ldmatrix per-thread selectors
    const int lr  = lane & 7;
    const int lhk = (lane >> 3) & 1;
    const int lhi = lane >> 4;

    // prologue: stages 0..NSTAGE-2
#pragma unroll
    for (int t = 0; t < NSTAGE - 1; t++) {
        if (t < nkt) load_tile(t);
        CP_COMMIT();
    }
    CP_WAIT1();
    __syncthreads();

    for (int kt = 0; kt < nkt; kt++) {
        // issue loads for kt+NSTAGE-1 (buffer of tile kt-1: safe, one sync ago)
        if (kt + NSTAGE - 1 < nkt) load_tile(kt + NSTAGE - 1);
        CP_COMMIT();

        const int st = kt % NSTAGE;
        const uint32_t asb = a_sm + (uint32_t)st * STG_WORDS * 4;
        const uint32_t bsb = b_sm + (uint32_t)st * STG_WORDS * 4;

#pragma unroll
        for (int ks = 0; ks < 8; ks++) {
            uint32_t af[2][4];
#pragma unroll
            for (int mt = 0; mt < 2; mt++) {
                const int row = wm + mt * 16 + lhk * 8 + lr;
                const int chk = ks * 2 + lhi;
                const uint32_t addr = asb + (uint32_t)row * 256
                                    + (uint32_t)((chk ^ (row & 7)) * 16);
                ldsm_x4(af[mt][0], af[mt][1], af[mt][2], af[mt][3], addr);
            }
            uint32_t bf[8][2];
#pragma unroll
            for (int p = 0; p < 4; p++) {
                const int row = wn + p * 16 + lhi * 8 + lr;
                const int chk = ks * 2 + lhk;
                const uint32_t addr = bsb + (uint32_t)row * 256
                                    + (uint32_t)((chk ^ (row & 7)) * 16);
                ldsm_x4(bf[2 * p][0], bf[2 * p][1], bf[2 * p + 1][0], bf[2 * p + 1][1], addr);
            }
#pragma unroll
            for (int mt = 0; mt < 2; mt++)
#pragma unroll
                for (int nt = 0; nt < 8; nt++)
                    mma_tf32(acc[mt][nt], af[mt], bf[nt]);
        }

        CP_WAIT1();
        __syncthreads();
    }

    // ---- epilogue ----
#pragma unroll
    for (int mt = 0; mt < 2; mt++) {
#pragma unroll
        for (int nt = 0; nt < 8; nt++) {
            const int col = n0 + wn + nt * 8 + 2 * tig;
            if (col < N) {
                const int r0 = m0 + wm + mt * 16 + g;
                float o0 = alpha * acc[mt][nt][0], o1 = alpha * acc[mt][nt][1];
                float o2 = alpha * acc[mt][nt][2], o3 = alpha * acc[mt][nt][3];
                if (ROUNDC) {
                    o0 = round_tf32(o0); o1 = round_tf32(o1);
                    o2 = round_tf32(o2); o3 = round_tf32(o3);
                }
                *(float2*)&C[(size_t)r0 * ldc + col]       = make_float2(o0, o1);
                *(float2*)&C[(size_t)(r0 + 8) * ldc + col] = make_float2(o2, o3);
            }
        }
    }
}

// ---------------- rmsnorm (writes tf32-rounded output) ----------------
__global__ void rmsnorm_kernel(float* __restrict__ x, const float* __restrict__ g,
                               int rowstride, int w)
{
    const int row = blockIdx.x;
    float* p = x + (size_t)row * rowstride;
    __shared__ float red[256];
    float s = 0.0f;
    for (int c = threadIdx.x; c < w; c += 256) { float v = p[c]; s += v * v; }
    red[threadIdx.x] = s;
    __syncthreads();
    for (int o = 128; o > 0; o >>= 1) {
        if (threadIdx.x < o) red[threadIdx.x] += red[threadIdx.x + o];
        __syncthreads();
    }
    const float r = rsqrtf(red[0] / (float)w + 1e-6f);
    for (int c = threadIdx.x; c < w; c += 256)
        p[c] = round_tf32(p[c] * r * g[c]);
}

// ---------------- interleaved RoPE ----------------
__global__ void rope_kernel(float* __restrict__ base, const int* __restrict__ positions,
                            int rowstride, int headstride, int offset, int round_nope)
{
    const int t = blockIdx.x;
    const int h = blockIdx.y;
    const int i = threadIdx.x;  // 0..31
    float* hp = base + (size_t)t * rowstride + h * headstride;
    float* p = hp + offset;
    const float pos = (float)positions[t];
    const float inv = powf(10000.0f, -(float)(2 * i) / 64.0f);
    float sn, cs;
    sincosf(pos * inv, &sn, &cs);
    const float x1 = p[2 * i];
    const float x2 = p[2 * i + 1];
    p[2 * i]     = round_tf32(x1 * cs - x2 * sn);
    p[2 * i + 1] = round_tf32(x1 * sn + x2 * cs);
    if (round_nope) {
#pragma unroll
        for (int j = 0; j < 4; j++)
            hp[i * 4 + j] = round_tf32(hp[i * 4 + j]);
    }
}

// ---------------- build k_full ----------------
__global__ void kfull_kernel()
{
    const int t = blockIdx.x;
    const int h = blockIdx.y;
    const int d = threadIdx.x;
    float v;
    if (d < DN) v = g_kv[(size_t)t * (NH * (DN + DV)) + h * (DN + DV) + d];
    else        v = g_kva[(size_t)t * (KVL + DR) + KVL + (d - DN)];
    g_kfull[(size_t)t * (NH * DH) + h * DH + d] = v;
}

// ---------------- causal softmax: stores rounded exp, sums unrounded ----------------
__global__ void softmax_kernel(const int* __restrict__ positions)
{
    const int q = blockIdx.x;
    const int h = blockIdx.y;
    float* row = g_s + ((size_t)h * T_TOK + q) * T_TOK;
    const int pq = positions[q];
    const int jmax = ((q >> 7) + 1) << 7;
    __shared__ float red[256];
    const int tid = threadIdx.x;

    float m = -INFINITY;
    for (int j = tid; j < jmax; j += 256)
        if (positions[j] <= pq) m = fmaxf(m, row[j]);
    red[tid] = m;
    __syncthreads();
    for (int o = 128; o > 0; o >>= 1) {
        if (tid < o) red[tid] = fmaxf(red[tid], red[tid + o]);
        __syncthreads();
    }
    m = red[0];
    __syncthreads();

    float s = 0.0f;
    for (int j = tid; j < jmax; j += 256) {
        float v = 0.0f;
        if (positions[j] <= pq) { v = __expf(row[j] - m); s += v; }
        row[j] = round_tf32(v);
    }
    red[tid] = s;
    __syncthreads();
    for (int o = 128; o > 0; o >>= 1) {
        if (tid < o) red[tid] += red[tid + o];
        __syncthreads();
    }
    if (tid == 0) g_rowsum[(size_t)h * T_TOK + q] = red[0];
}

// ---------------- normalize attn rows (writes rounded) ----------------
__global__ void attn_norm_kernel()
{
    const int t = blockIdx.x;
    float* p = g_attn + (size_t)t * (NH * DV);
    for (int c = threadIdx.x; c < NH * DV; c += 256) {
        const int h = c >> 7;
        p[c] = round_tf32(p[c] * (1.0f / g_rowsum[(size_t)h * T_TOK + t]));
    }
}

// ---------------- launcher ----------------
extern "C" void kernel_launch(void* const* d_in, const int* in_sizes, int n_in,
                              void* d_out, int out_size)
{
    const int*   positions = (const int*)  d_in[0];
    const float* hidden    = (const float*)d_in[1];
    const float* wq_a      = (const float*)d_in[2];
    const float* gq        = (const float*)d_in[3];
    const float* wq_b      = (const float*)d_in[4];
    const float* wkv_a     = (const float*)d_in[5];
    const float* gkv       = (const float*)d_in[6];
    const float* wkv_b     = (const float*)d_in[7];
    const float* wo        = (const float*)d_in[8];
    float* out = (float*)d_out;

    float *qa, *q, *kva, *kv, *kfull, *s, *attn, *vt;
    float *hidr, *wqa, *wqb, *wkva, *wkvb, *wor;
    cudaGetSymbolAddress((void**)&qa,    g_qa);
    cudaGetSymbolAddress((void**)&q,     g_q);
    cudaGetSymbolAddress((void**)&kva,   g_kva);
    cudaGetSymbolAddress((void**)&kv,    g_kv);
    cudaGetSymbolAddress((void**)&kfull, g_kfull);
    cudaGetSymbolAddress((void**)&s,     g_s);
    cudaGetSymbolAddress((void**)&attn,  g_attn);
    cudaGetSymbolAddress((void**)&vt,    g_vt);
    cudaGetSymbolAddress((void**)&hidr,  g_hidr);
    cudaGetSymbolAddress((void**)&wqa,   g_wqa);
    cudaGetSymbolAddress((void**)&wqb,   g_wqb);
    cudaGetSymbolAddress((void**)&wkva,  g_wkva);
    cudaGetSymbolAddress((void**)&wkvb,  g_wkvb);
    cudaGetSymbolAddress((void**)&wor,   g_wo);

    static bool attr_done = false;
    if (!attr_done) {
        cudaFuncSetAttribute(tmma_gemm<false,false,false>,
            cudaFuncAttributeMaxDynamicSharedMemorySize, GEMM_SMEM_BYTES);
        cudaFuncSetAttribute(tmma_gemm<false,false,true>,
            cudaFuncAttributeMaxDynamicSharedMemorySize, GEMM_SMEM_BYTES);
        cudaFuncSetAttribute(tmma_gemm<true,false,false>,
            cudaFuncAttributeMaxDynamicSharedMemorySize, GEMM_SMEM_BYTES);
        cudaFuncSetAttribute(tmma_gemm<false,true,false>,
            cudaFuncAttributeMaxDynamicSharedMemorySize, GEMM_SMEM_BYTES);
        attr_done = true;
    }

    const float scale = 1.0f / sqrtf((float)DH);
    const dim3 blk(256);
    const int  shm = GEMM_SMEM_BYTES;
    const dim3 tblk(32, 8);

    // 0. round hidden; round+transpose weights to [n][k]
    round_pass_kernel<<<1024, 256>>>(hidden, hidr, (int)((size_t)T_TOK * HID / 4));
    transpose_round_kernel<<<dim3(QL/32, HID/32), tblk>>>(wq_a, wqa, HID, QL);
    transpose_round_kernel<<<dim3(NH*DH/32, QL/32), tblk>>>(wq_b, wqb, QL, NH*DH);
    transpose_round_kernel<<<dim3((KVL+DR)/32, HID/32), tblk>>>(wkv_a, wkva, HID, KVL+DR);
    transpose_round_kernel<<<dim3(NH*(DN+DV)/32, KVL/32), tblk>>>(wkv_b, wkvb, KVL, NH*(DN+DV));
    transpose_round_kernel<<<dim3(HID/32, NH*DV/32), tblk>>>(wo, wor, NH*DV, HID);

    // 1. qa = hidr @ wqa^T           [2048,1536] K=4096
    tmma_gemm<false,false,false><<<dim3(QL/128, T_TOK/128, 1), blk, shm>>>(
        hidr, wqa, qa, T_TOK, QL, HID, HID, HID, QL, 0, 0, 0, 1.0f);

    // 2. rmsnorm(qa) -> rounded
    rmsnorm_kernel<<<T_TOK, 256>>>(qa, gq, QL, QL);

    // 3. q = qln @ wqb^T             [2048,6144] K=1536
    tmma_gemm<false,false,false><<<dim3(NH*DH/128, T_TOK/128, 1), blk, shm>>>(
        qa, wqb, q, T_TOK, NH*DH, QL, QL, QL, NH*DH, 0, 0, 0, 1.0f);

    // 4. kva = hidr @ wkva^T         [2048,576] K=4096
    tmma_gemm<false,false,false><<<dim3((KVL+DR+127)/128, T_TOK/128, 1), blk, shm>>>(
        hidr, wkva, kva, T_TOK, KVL+DR, HID, HID, HID, KVL+DR, 0, 0, 0, 1.0f);

    // 5. rmsnorm first 512 cols of kva -> rounded
    rmsnorm_kernel<<<T_TOK, 256>>>(kva, gkv, KVL+DR, KVL);

    // 6. kv = ckv_ln @ wkvb^T        [2048,8192] K=512  (epilogue rounds)
    tmma_gemm<false,false,true><<<dim3(NH*(DN+DV)/128, T_TOK/128, 1), blk, shm>>>(
        kva, wkvb, kv, T_TOK, NH*(DN+DV), KVL, KVL+DR, KVL, NH*(DN+DV),
        0, 0, 0, 1.0f);

    // 7. rope q_pe (+ round q_nope)
    rope_kernel<<<dim3(T_TOK, NH), 32>>>(q, positions, NH*DH, DH, DN, 1);

    // 8. rope k_pe
    rope_kernel<<<dim3(T_TOK, 1), 32>>>(kva, positions, KVL+DR, 0, KVL, 0);

    // 9. k_full + v^T
    kfull_kernel<<<dim3(T_TOK, NH), DH>>>();
    vtrans_kernel<<<dim3(T_TOK/32, DV/32, NH), tblk>>>();

    // 10. scores[h] = scale * q[h] @ kfull[h]^T   (causal tile skip)
    tmma_gemm<true,false,false><<<dim3(T_TOK/128, T_TOK/128, NH), blk, shm>>>(
        q, kfull, s, T_TOK, T_TOK, DH, NH*DH, NH*DH, T_TOK,
        (long long)DH, (long long)DH, (long long)T_TOK*T_TOK, scale);

    // 11. causal softmax (stores rounded exp, sums fp32)
    softmax_kernel<<<dim3(T_TOK, NH), 256>>>(positions);

    // 12. attn[h] = exp_probs[h] @ vt[h]^T   (causal K clamp)
    tmma_gemm<false,true,false><<<dim3(1, T_TOK/128, NH), blk, shm>>>(
        s, vt, attn, T_TOK, DV, T_TOK, T_TOK, T_TOK, NH*DV,
        (long long)T_TOK*T_TOK, (long long)DV*T_TOK, (long long)DV, 1.0f);

    // 12b. normalize attn -> rounded
    attn_norm_kernel<<<T_TOK, 256>>>();

    // 13. out = attn @ wo^T           [2048,4096]
    tmma_gemm<false,false,false><<<dim3(HID/128, T_TOK/128, 1), blk, shm>>>(
        attn, wor, out, T_TOK, HID, NH*DV, NH*DV, NH*DV, HID, 0, 0, 0, 1.0f);
}